// round 7
// baseline (speedup 1.0000x reference)
#include <cuda_runtime.h>
#include <cuda_bf16.h>
#include <cuda_fp16.h>
#include <math.h>

#define N_NODES 100000
#define N_EDGES 800000
#define D_DATA  100
#define H_DIM   256
#define N_CLS   47
#define K_STEPS 10
#define D_VEC   25          // D_DATA / 4 float4s per row

// ---------------- static device scratch ----------------
__device__ float g_buf0[(size_t)N_NODES * D_DATA];   // 40 MB
__device__ float g_buf1[(size_t)N_NODES * D_DATA];   // 40 MB
__device__ int   d_cnt[N_NODES];
__device__ int   d_ptr[N_NODES + 1];
__device__ int   d_cursor[N_NODES];
__device__ float d_norm[N_NODES];
__device__ float d_n2[N_NODES];
__device__ int   d_csr[N_EDGES];

// ---------------- f32x2 packed helpers ----------------
#define FMA2(acc, a, b) \
    asm("fma.rn.f32x2 %0, %1, %2, %0;" : "+l"(acc) : "l"(a), "l"(b))
#define PACK_DUP(dst, v) \
    asm("mov.b64 %0, {%1, %1};" : "=l"(dst) : "r"(__float_as_uint(v)))
#define PACK2(dst, lo, hi) \
    asm("mov.b64 %0, {%1, %2};" : "=l"(dst) : "f"(lo), "f"(hi))
#define UNPACK2(lo, hi, v) \
    asm("mov.b64 {%0, %1}, %2;" : "=f"(lo), "=f"(hi) : "l"(v))

// ---------------- CSR build ----------------
// d_cnt is zero at entry of every call: zero-initialized at load, and
// re-zeroed by fill_kernel at the end of each call (deterministic state).
__global__ void count_kernel(const int* __restrict__ dst) {
    int e = blockIdx.x * blockDim.x + threadIdx.x;
    if (e < N_EDGES) atomicAdd(&d_cnt[dst[e]], 1);
}

// scan + norm fused
#define SCAN_T 1024
#define SCAN_CH 98   // ceil(100000/1024)
__global__ void scan_kernel() {
    __shared__ int part[SCAN_T];
    int t = threadIdx.x;
    int beg = t * SCAN_CH;
    int end = beg + SCAN_CH; if (end > N_NODES) end = N_NODES;
    if (beg > N_NODES) beg = N_NODES;
    int s = 0;
    for (int i = beg; i < end; i++) s += d_cnt[i];
    part[t] = s;
    __syncthreads();
    for (int off = 1; off < SCAN_T; off <<= 1) {
        int v = (t >= off) ? part[t - off] : 0;
        __syncthreads();
        part[t] += v;
        __syncthreads();
    }
    int run = part[t] - s;
    for (int i = beg; i < end; i++) {
        d_ptr[i] = run;
        d_cursor[i] = run;
        int c = d_cnt[i];
        run += c;
        float nm = rsqrtf(fmaxf((float)c, 1.0f));
        d_norm[i] = nm;
        d_n2[i] = nm * nm;
    }
    if (t == SCAN_T - 1) d_ptr[N_NODES] = part[SCAN_T - 1];
}

// scatter src ids into CSR; also zero d_cnt for the next call
__global__ void fill_kernel(const int* __restrict__ src, const int* __restrict__ dst) {
    int e = blockIdx.x * blockDim.x + threadIdx.x;
    if (e < N_EDGES) {
        int d = dst[e];
        int p = atomicAdd(&d_cursor[d], 1);
        d_csr[p] = src[e];
    }
    if (e < N_NODES) d_cnt[e] = 0;
}

// ---------------- propagation ----------------
// First step fused with init: g1 = 0.9*n2*sum_e (norm[src]*x[src]) + 0.1*norm*x
__global__ void prop_first_kernel(const float4* __restrict__ x,
                                  float4* __restrict__ gout) {
    int warp = (blockIdx.x * blockDim.x + threadIdx.x) >> 5;
    int lane = threadIdx.x & 31;
    if (warp >= N_NODES) return;
    int beg = d_ptr[warp];
    int end = d_ptr[warp + 1];

    float a0 = 0.f, a1 = 0.f, a2 = 0.f, a3 = 0.f;
    bool act = lane < D_VEC;

    for (int base = beg; base < end; base += 32) {
        int n = end - base; if (n > 32) n = 32;
        int idx = (lane < n) ? d_csr[base + lane] : 0;
        #pragma unroll 4
        for (int e = 0; e < n; e++) {
            int s = __shfl_sync(0xffffffffu, idx, e);
            float ns = __ldg(&d_norm[s]);
            if (act) {
                float4 v = x[s * D_VEC + lane];
                a0 += ns * v.x; a1 += ns * v.y; a2 += ns * v.z; a3 += ns * v.w;
            }
        }
    }

    float s1 = 0.9f * d_n2[warp];
    float s2 = 0.1f * d_norm[warp];
    if (act) {
        float4 xv = x[warp * D_VEC + lane];
        float4 o;
        o.x = s1 * a0 + s2 * xv.x;
        o.y = s1 * a1 + s2 * xv.y;
        o.z = s1 * a2 + s2 * xv.z;
        o.w = s1 * a3 + s2 * xv.w;
        gout[warp * D_VEC + lane] = o;
    }
}

// Steps 2..K. gout = s1 * sum_e gin[src] + s2 * x
__global__ void prop_kernel(const float4* __restrict__ gin,
                            float4* __restrict__ gout,
                            const float4* __restrict__ x,
                            int last) {
    int warp = (blockIdx.x * blockDim.x + threadIdx.x) >> 5;
    int lane = threadIdx.x & 31;
    if (warp >= N_NODES) return;
    int beg = d_ptr[warp];
    int end = d_ptr[warp + 1];

    float a0 = 0.f, a1 = 0.f, a2 = 0.f, a3 = 0.f;
    bool act = lane < D_VEC;

    for (int base = beg; base < end; base += 32) {
        int n = end - base; if (n > 32) n = 32;
        int idx = (lane < n) ? d_csr[base + lane] : 0;
        #pragma unroll 4
        for (int e = 0; e < n; e++) {
            int s = __shfl_sync(0xffffffffu, idx, e);
            if (act) {
                float4 v = gin[s * D_VEC + lane];
                a0 += v.x; a1 += v.y; a2 += v.z; a3 += v.w;
            }
        }
    }

    float ni = d_norm[warp];
    float s1, s2;
    if (last) { s1 = 0.9f * ni;         s2 = 0.1f; }
    else      { s1 = 0.9f * d_n2[warp]; s2 = 0.1f * ni; }

    if (act) {
        float4 xv = __ldcs(&x[warp * D_VEC + lane]);
        float4 o;
        o.x = s1 * a0 + s2 * xv.x;
        o.y = s1 * a1 + s2 * xv.y;
        o.z = s1 * a2 + s2 * xv.z;
        o.w = s1 * a3 + s2 * xv.w;
        if (last) __stcs(&gout[warp * D_VEC + lane], o);   // h consumed once
        else      gout[warp * D_VEC + lane] = o;
    }
}

// ---------------- fused MLP: logits = relu(h@W1+b1)@W2+b2 ----------------
// TM=64, 512 threads (16 warps/SM -> 4 per SMSP), per-thread 2m x 16j (FFMA2).
// hs fp16, W2 staged fp16, zs fp32. Conflict-free layouts.
#define TM 64
#define HS_STRIDE 104        // halves per row
#define W2H_STRIDE 258       // halves per class row
#define MLP_THREADS 512

// byte layout
#define SMB_W1P  (D_DATA * H_DIM * 4)          // 102400
#define SMB_W2H  (48 * W2H_STRIDE * 2)         // 24768
#define SMB_B1   (H_DIM * 4)                   // 1024
#define SMB_B2   (48 * 4)                      // 192
#define SMB_HS   (TM * HS_STRIDE * 2)          // 13312
#define SMB_ZS   (TM * H_DIM * 4)              // 65536
#define MLP_SMEM_BYTES (SMB_W1P + SMB_W2H + SMB_B1 + SMB_B2 + SMB_HS + SMB_ZS)  // 207232

__global__ void __launch_bounds__(MLP_THREADS, 1)
mlp_kernel(const float* __restrict__ h,
           const float* __restrict__ W1, const float* __restrict__ b1,
           const float* __restrict__ W2, const float* __restrict__ b2,
           float* __restrict__ out) {
    extern __shared__ char smraw[];
    float*  W1p  = (float*)smraw;                              // permuted W1
    __half* W2h  = (__half*)(smraw + SMB_W1P);                 // [c][j] fp16
    float*  b1s  = (float*)(smraw + SMB_W1P + SMB_W2H);
    float*  b2s  = (float*)(smraw + SMB_W1P + SMB_W2H + SMB_B1);
    __half* hs   = (__half*)(smraw + SMB_W1P + SMB_W2H + SMB_B1 + SMB_B2);
    float*  zs   = (float*)(smraw + SMB_W1P + SMB_W2H + SMB_B1 + SMB_B2 + SMB_HS);

    int tid = threadIdx.x;

    // stage W1 permuted: 16B unit (d,k,jg) -> (d*4+k)*16+jg
    {
        const float4* W1v = (const float4*)W1;
        float4* W1pv = (float4*)W1p;
        for (int i = tid; i < D_DATA * 64; i += MLP_THREADS) {
            int d = i >> 6, u = i & 63;
            int k = u & 3, jg = u >> 2;
            W1pv[(d * 4 + k) * 16 + jg] = W1v[i];
        }
    }
    // stage W2 transposed fp16
    for (int i = tid; i < 48 * H_DIM; i += MLP_THREADS) {
        int c = i >> 8, j = i & 255;
        W2h[c * W2H_STRIDE + j] = __float2half((c < N_CLS) ? W2[j * N_CLS + c] : 0.f);
    }
    for (int i = tid; i < H_DIM; i += MLP_THREADS) b1s[i] = b1[i];
    if (tid < 48) b2s[tid] = (tid < N_CLS) ? b2[tid] : 0.f;
    __syncthreads();

    // phase-1 mapping: jg = tid&15 (16j each), mg = tid>>4 in 0..31 (2m each)
    int jg = tid & 15, mg = tid >> 4;
    int j0 = jg * 16, m0 = mg * 2;
    // phase-2 mapping: cg = tid&15 (3c each), mg2 = tid>>4 (2m each)
    int cg = tid & 15, mg2 = tid >> 4;
    int c0 = cg * 3, mm0 = mg2 * 2;

    const ulonglong2* W1q = (const ulonglong2*)W1p;

    int n_tiles = (N_NODES + TM - 1) / TM;   // 1563
    for (int tile = blockIdx.x; tile < n_tiles; tile += gridDim.x) {
        int node0 = tile * TM;

        // stream h tile -> fp16 smem
        {
            const float4* hrow = (const float4*)h;
            for (int i = tid; i < TM * D_VEC; i += MLP_THREADS) {
                int m = i / D_VEC, d4 = i - m * D_VEC;
                int node = node0 + m;
                float4 v = make_float4(0.f, 0.f, 0.f, 0.f);
                if (node < N_NODES) v = __ldcs(&hrow[(size_t)node * D_VEC + d4]);
                __half2 p0 = __floats2half2_rn(v.x, v.y);
                __half2 p1 = __floats2half2_rn(v.z, v.w);
                uint2 pk;
                pk.x = *(unsigned int*)&p0;
                pk.y = *(unsigned int*)&p1;
                *(uint2*)((char*)hs + (size_t)m * (HS_STRIDE * 2) + d4 * 8) = pk;
            }
        }
        __syncthreads();

        // ---- phase 1: z = relu(h@W1 + b1), 2m x 16j per thread ----
        unsigned long long acc[2][8];
        #pragma unroll
        for (int k = 0; k < 4; k++) {
            unsigned long long blo = *(const unsigned long long*)(b1s + j0 + k * 4);
            unsigned long long bhi = *(const unsigned long long*)(b1s + j0 + k * 4 + 2);
            #pragma unroll
            for (int mi = 0; mi < 2; mi++) {
                acc[mi][k * 2]     = blo;
                acc[mi][k * 2 + 1] = bhi;
            }
        }

        #pragma unroll 2
        for (int d = 0; d < D_DATA; d++) {
            unsigned long long w[8];
            #pragma unroll
            for (int k = 0; k < 4; k++) {
                ulonglong2 wq = W1q[(d * 4 + k) * 16 + jg];
                w[k * 2] = wq.x; w[k * 2 + 1] = wq.y;
            }
            unsigned long long hv2[2];
            #pragma unroll
            for (int mi = 0; mi < 2; mi++) {
                float hv = __half2float(hs[(m0 + mi) * HS_STRIDE + d]);
                PACK_DUP(hv2[mi], hv);
            }
            #pragma unroll
            for (int mi = 0; mi < 2; mi++)
                #pragma unroll
                for (int p = 0; p < 8; p++)
                    FMA2(acc[mi][p], hv2[mi], w[p]);
        }

        #pragma unroll
        for (int mi = 0; mi < 2; mi++) {
            #pragma unroll
            for (int p = 0; p < 8; p++) {
                float lo, hi;
                UNPACK2(lo, hi, acc[mi][p]);
                int j = j0 + (p >> 1) * 4 + (p & 1) * 2;
                float2 zv = make_float2(fmaxf(lo, 0.f), fmaxf(hi, 0.f));
                *(float2*)(zs + (m0 + mi) * H_DIM + j) = zv;
            }
        }
        __syncthreads();

        // ---- phase 2: logits = z@W2 + b2, 2m x 3c per thread ----
        unsigned long long a2[2][3];
        #pragma unroll
        for (int mi = 0; mi < 2; mi++)
            #pragma unroll
            for (int ci = 0; ci < 3; ci++) a2[mi][ci] = 0ull;

        #pragma unroll 4
        for (int j2 = 0; j2 < H_DIM / 2; j2++) {
            unsigned long long zz[2], ww[3];
            #pragma unroll
            for (int mi = 0; mi < 2; mi++)
                zz[mi] = *(const unsigned long long*)(zs + (mm0 + mi) * H_DIM + j2 * 2);
            #pragma unroll
            for (int ci = 0; ci < 3; ci++) {
                __half2 wh = *(const __half2*)(W2h + (c0 + ci) * W2H_STRIDE + j2 * 2);
                float2 wf = __half22float2(wh);
                PACK2(ww[ci], wf.x, wf.y);
            }
            #pragma unroll
            for (int mi = 0; mi < 2; mi++)
                #pragma unroll
                for (int ci = 0; ci < 3; ci++)
                    FMA2(a2[mi][ci], zz[mi], ww[ci]);
        }

        #pragma unroll
        for (int mi = 0; mi < 2; mi++) {
            int node = node0 + mm0 + mi;
            if (node < N_NODES) {
                #pragma unroll
                for (int ci = 0; ci < 3; ci++) {
                    int c = c0 + ci;
                    if (c < N_CLS) {
                        float lo, hi;
                        UNPACK2(lo, hi, a2[mi][ci]);
                        out[(size_t)node * N_CLS + c] = lo + hi + b2s[c];
                    }
                }
            }
        }
        __syncthreads();
    }
}

// ---------------- launch ----------------
extern "C" void kernel_launch(void* const* d_in, const int* in_sizes, int n_in,
                              void* d_out, int out_size) {
    const float* x   = (const float*)d_in[0];
    const int*   src = (const int*)d_in[1];
    const int*   dst = (const int*)d_in[2];
    const float* W1  = (const float*)d_in[3];
    const float* b1  = (const float*)d_in[4];
    const float* W2  = (const float*)d_in[5];
    const float* b2  = (const float*)d_in[6];
    float* out = (float*)d_out;

    cudaFuncSetAttribute(mlp_kernel, cudaFuncAttributeMaxDynamicSharedMemorySize,
                         MLP_SMEM_BYTES);

    float* p0 = nullptr;
    float* p1 = nullptr;
    cudaGetSymbolAddress((void**)&p0, g_buf0);
    cudaGetSymbolAddress((void**)&p1, g_buf1);

    int nb_edges = (N_EDGES + 255) / 256;
    int nb_prop = (N_NODES * 32 + 255) / 256;   // one warp per node

    count_kernel<<<nb_edges, 256>>>(dst);                 // launch 0
    scan_kernel<<<1, SCAN_T>>>();                         // launch 1 (scan+norm)
    fill_kernel<<<nb_edges, 256>>>(src, dst);             // launch 2 (+zero cnt)

    // t = 0 fused with init: writes g_buf1                // launch 3 (profiled)
    prop_first_kernel<<<nb_prop, 256>>>((const float4*)x, (float4*)p1);

    // t = 1..9: ping-pong; t odd reads p1 writes p0, ...
    for (int t = 1; t < K_STEPS; t++) {
        const float* gin = (t & 1) ? p1 : p0;
        float* gout      = (t & 1) ? p0 : p1;
        prop_kernel<<<nb_prop, 256>>>((const float4*)gin, (float4*)gout,
                                      (const float4*)x, (t == K_STEPS - 1) ? 1 : 0);
    }
    // t=9 (odd) wrote p0 -> h lives in g_buf0
    mlp_kernel<<<148, MLP_THREADS, MLP_SMEM_BYTES>>>(p0, W1, b1, W2, b2, out);
}

// round 9
// speedup vs baseline: 1.2384x; 1.2384x over previous
#include <cuda_runtime.h>
#include <cuda_bf16.h>
#include <cuda_fp16.h>
#include <math.h>
#include <stdint.h>

#define N_NODES 100000
#define N_EDGES 800000
#define D_DATA  100
#define H_DIM   256
#define N_CLS   47
#define K_STEPS 10
#define D_VEC   25          // D_DATA / 4 float4s per row

// ---------------- static device scratch ----------------
__device__ float g_buf0[(size_t)N_NODES * D_DATA];   // 40 MB
__device__ float g_buf1[(size_t)N_NODES * D_DATA];   // 40 MB
__device__ int   d_cnt[N_NODES];
__device__ int   d_ptr[N_NODES + 1];
__device__ int   d_cursor[N_NODES];
__device__ float d_norm[N_NODES];
__device__ float d_n2[N_NODES];
__device__ int   d_csr[N_EDGES];

// ---------------- CSR build ----------------
// d_cnt is zero at entry of every call (zero-init at load; fill_kernel re-zeros).
__global__ void count_kernel(const int* __restrict__ dst) {
    int e = blockIdx.x * blockDim.x + threadIdx.x;
    if (e < N_EDGES) atomicAdd(&d_cnt[dst[e]], 1);
}

#define SCAN_T 1024
#define SCAN_CH 98
__global__ void scan_kernel() {
    __shared__ int part[SCAN_T];
    int t = threadIdx.x;
    int beg = t * SCAN_CH;
    int end = beg + SCAN_CH; if (end > N_NODES) end = N_NODES;
    if (beg > N_NODES) beg = N_NODES;
    int s = 0;
    for (int i = beg; i < end; i++) s += d_cnt[i];
    part[t] = s;
    __syncthreads();
    for (int off = 1; off < SCAN_T; off <<= 1) {
        int v = (t >= off) ? part[t - off] : 0;
        __syncthreads();
        part[t] += v;
        __syncthreads();
    }
    int run = part[t] - s;
    for (int i = beg; i < end; i++) {
        d_ptr[i] = run;
        d_cursor[i] = run;
        int c = d_cnt[i];
        run += c;
        float nm = rsqrtf(fmaxf((float)c, 1.0f));
        d_norm[i] = nm;
        d_n2[i] = nm * nm;
    }
    if (t == SCAN_T - 1) d_ptr[N_NODES] = part[SCAN_T - 1];
}

__global__ void fill_kernel(const int* __restrict__ src, const int* __restrict__ dst) {
    int e = blockIdx.x * blockDim.x + threadIdx.x;
    if (e < N_EDGES) {
        int d = dst[e];
        int p = atomicAdd(&d_cursor[d], 1);
        d_csr[p] = src[e];
    }
    if (e < N_NODES) d_cnt[e] = 0;
}

// ---------------- propagation (measured-best variants) ----------------
__global__ void prop_first_kernel(const float4* __restrict__ x,
                                  float4* __restrict__ gout) {
    int warp = (blockIdx.x * blockDim.x + threadIdx.x) >> 5;
    int lane = threadIdx.x & 31;
    if (warp >= N_NODES) return;
    int beg = d_ptr[warp];
    int end = d_ptr[warp + 1];

    float a0 = 0.f, a1 = 0.f, a2 = 0.f, a3 = 0.f;
    bool act = lane < D_VEC;

    for (int base = beg; base < end; base += 32) {
        int n = end - base; if (n > 32) n = 32;
        int idx = (lane < n) ? d_csr[base + lane] : 0;
        #pragma unroll 4
        for (int e = 0; e < n; e++) {
            int s = __shfl_sync(0xffffffffu, idx, e);
            float ns = __ldg(&d_norm[s]);
            if (act) {
                float4 v = x[s * D_VEC + lane];
                a0 += ns * v.x; a1 += ns * v.y; a2 += ns * v.z; a3 += ns * v.w;
            }
        }
    }

    float s1 = 0.9f * d_n2[warp];
    float s2 = 0.1f * d_norm[warp];
    if (act) {
        float4 xv = x[warp * D_VEC + lane];
        float4 o;
        o.x = s1 * a0 + s2 * xv.x;
        o.y = s1 * a1 + s2 * xv.y;
        o.z = s1 * a2 + s2 * xv.z;
        o.w = s1 * a3 + s2 * xv.w;
        gout[warp * D_VEC + lane] = o;
    }
}

__global__ void prop_kernel(const float4* __restrict__ gin,
                            float4* __restrict__ gout,
                            const float4* __restrict__ x,
                            int last) {
    int warp = (blockIdx.x * blockDim.x + threadIdx.x) >> 5;
    int lane = threadIdx.x & 31;
    if (warp >= N_NODES) return;
    int beg = d_ptr[warp];
    int end = d_ptr[warp + 1];

    float a0 = 0.f, a1 = 0.f, a2 = 0.f, a3 = 0.f;
    bool act = lane < D_VEC;

    for (int base = beg; base < end; base += 32) {
        int n = end - base; if (n > 32) n = 32;
        int idx = (lane < n) ? d_csr[base + lane] : 0;
        #pragma unroll 4
        for (int e = 0; e < n; e++) {
            int s = __shfl_sync(0xffffffffu, idx, e);
            if (act) {
                float4 v = gin[s * D_VEC + lane];
                a0 += v.x; a1 += v.y; a2 += v.z; a3 += v.w;
            }
        }
    }

    float ni = d_norm[warp];
    float s1, s2;
    if (last) { s1 = 0.9f * ni;         s2 = 0.1f; }
    else      { s1 = 0.9f * d_n2[warp]; s2 = 0.1f * ni; }

    if (act) {
        float4 xv = __ldcs(&x[warp * D_VEC + lane]);
        float4 o;
        o.x = s1 * a0 + s2 * xv.x;
        o.y = s1 * a1 + s2 * xv.y;
        o.z = s1 * a2 + s2 * xv.z;
        o.w = s1 * a3 + s2 * xv.w;
        if (last) __stcs(&gout[warp * D_VEC + lane], o);
        else      gout[warp * D_VEC + lane] = o;
    }
}

// ---------------- MLP via warp-level mma.sync (fp16 in, fp32 accum) ----------
// Tile = 128 nodes per CTA, 8 warps; warp w owns rows [w*16, w*16+16).
// smem fp16 layouts (conflict-free fragment loads):
//   hs  [128 m][120 k]  (K=100 zero-padded to 112, stride 120 halves = 60 words)
//   W1T [256 j][120 k]
//   zs  [128 m][264 j]  (stride 264 halves = 132 words)
//   W2T [ 48 c][264 j]
#define TILE_M 128
#define MLP_THREADS 256
#define HS_W   60            // words per hs row
#define W1T_W  60
#define ZS_W   132
#define W2T_W  132

#define OFF_HS   0
#define OFF_W1T  30720
#define OFF_ZS   92160
#define OFF_W2T  159744
#define OFF_B1   185088
#define OFF_B2   186112
#define MLP_SMEM_BYTES 186304

__device__ __forceinline__ void mma16816(float& c0, float& c1, float& c2, float& c3,
                                         uint32_t a0, uint32_t a1, uint32_t a2, uint32_t a3,
                                         uint32_t b0, uint32_t b1) {
    asm volatile(
        "mma.sync.aligned.m16n8k16.row.col.f32.f16.f16.f32 "
        "{%0,%1,%2,%3}, {%4,%5,%6,%7}, {%8,%9}, {%0,%1,%2,%3};"
        : "+f"(c0), "+f"(c1), "+f"(c2), "+f"(c3)
        : "r"(a0), "r"(a1), "r"(a2), "r"(a3), "r"(b0), "r"(b1));
}

__device__ __forceinline__ uint32_t pack_h2(float lo, float hi) {
    __half2 h = __floats2half2_rn(lo, hi);
    return *(uint32_t*)&h;
}

__global__ void __launch_bounds__(MLP_THREADS, 1)
mlp_mma_kernel(const float* __restrict__ h,
               const float* __restrict__ W1, const float* __restrict__ b1,
               const float* __restrict__ W2, const float* __restrict__ b2,
               float* __restrict__ out) {
    extern __shared__ char smc[];
    uint32_t* hsW  = (uint32_t*)(smc + OFF_HS);
    uint32_t* w1W  = (uint32_t*)(smc + OFF_W1T);
    uint32_t* zsW  = (uint32_t*)(smc + OFF_ZS);
    uint32_t* w2W  = (uint32_t*)(smc + OFF_W2T);
    float*    b1s  = (float*)(smc + OFF_B1);
    float*    b2s  = (float*)(smc + OFF_B2);

    int tid = threadIdx.x;
    int wid = tid >> 5, lane = tid & 31;
    int gr = lane >> 2, tc = lane & 3;     // fragment row-group / thread-in-group
    int m0 = wid * 16;

    // ---- stage W1T [j][k], zero pad k >= 100 ----
    for (int i = tid; i < 256 * W1T_W; i += MLP_THREADS) {
        int j = i / W1T_W, kw = i % W1T_W;
        int k = kw * 2;
        float lo = (k     < D_DATA) ? W1[k * H_DIM + j]       : 0.f;
        float hi = (k + 1 < D_DATA) ? W1[(k + 1) * H_DIM + j] : 0.f;
        w1W[i] = pack_h2(lo, hi);
    }
    // ---- stage W2T [c][j], zero pad c >= 47, j >= 256 ----
    for (int i = tid; i < 48 * W2T_W; i += MLP_THREADS) {
        int c = i / W2T_W, jw = i % W2T_W;
        int j = jw * 2;
        float lo = (c < N_CLS && j     < H_DIM) ? W2[j * N_CLS + c]       : 0.f;
        float hi = (c < N_CLS && j + 1 < H_DIM) ? W2[(j + 1) * N_CLS + c] : 0.f;
        w2W[i] = pack_h2(lo, hi);
    }
    for (int i = tid; i < H_DIM; i += MLP_THREADS) b1s[i] = b1[i];
    if (tid < 48) b2s[tid] = (tid < N_CLS) ? b2[tid] : 0.f;
    __syncthreads();

    int n_tiles = (N_NODES + TILE_M - 1) / TILE_M;   // 782
    for (int tile = blockIdx.x; tile < n_tiles; tile += gridDim.x) {
        int node0 = tile * TILE_M;

        // ---- stage hs [m][k] fp16, zero pad ----
        for (int i = tid; i < TILE_M * HS_W; i += MLP_THREADS) {
            int m = i / HS_W, kw = i % HS_W;
            int k = kw * 2;
            int node = node0 + m;
            uint32_t v = 0;
            if (node < N_NODES && k < D_DATA) {
                float2 f = *(const float2*)(h + (size_t)node * D_DATA + k);
                v = pack_h2(f.x, f.y);
            }
            hsW[i] = v;
        }
        __syncthreads();

        // ---- phase 1: z = relu(h @ W1 + b1); 4 n-chunks of 64 ----
        #pragma unroll 1
        for (int ch = 0; ch < 4; ch++) {
            int n0 = ch * 64;
            float acc[8][4];
            #pragma unroll
            for (int nb = 0; nb < 8; nb++)
                #pragma unroll
                for (int q = 0; q < 4; q++) acc[nb][q] = 0.f;

            #pragma unroll
            for (int kb = 0; kb < 7; kb++) {
                int kwb = kb * 8 + tc;
                uint32_t a0 = hsW[(m0 + gr) * HS_W + kwb];
                uint32_t a1 = hsW[(m0 + gr + 8) * HS_W + kwb];
                uint32_t a2 = hsW[(m0 + gr) * HS_W + kwb + 4];
                uint32_t a3 = hsW[(m0 + gr + 8) * HS_W + kwb + 4];
                #pragma unroll
                for (int nb = 0; nb < 8; nb++) {
                    int j = n0 + nb * 8 + gr;
                    uint32_t b0 = w1W[j * W1T_W + kwb];
                    uint32_t b1f = w1W[j * W1T_W + kwb + 4];
                    mma16816(acc[nb][0], acc[nb][1], acc[nb][2], acc[nb][3],
                             a0, a1, a2, a3, b0, b1f);
                }
            }
            // epilogue: bias + relu -> zs fp16
            #pragma unroll
            for (int nb = 0; nb < 8; nb++) {
                int j = n0 + nb * 8 + 2 * tc;
                float2 bb = *(const float2*)(b1s + j);
                float f0 = fmaxf(acc[nb][0] + bb.x, 0.f);
                float f1 = fmaxf(acc[nb][1] + bb.y, 0.f);
                float f2 = fmaxf(acc[nb][2] + bb.x, 0.f);
                float f3 = fmaxf(acc[nb][3] + bb.y, 0.f);
                int jw = (n0 + nb * 8) / 2 + tc;
                zsW[(m0 + gr) * ZS_W + jw]     = pack_h2(f0, f1);
                zsW[(m0 + gr + 8) * ZS_W + jw] = pack_h2(f2, f3);
            }
        }
        __syncwarp();

        // ---- phase 2: logits = z @ W2 + b2 ----
        {
            float acc[6][4];
            #pragma unroll
            for (int nb = 0; nb < 6; nb++)
                #pragma unroll
                for (int q = 0; q < 4; q++) acc[nb][q] = 0.f;

            #pragma unroll 4
            for (int kb = 0; kb < 16; kb++) {
                int kwb = kb * 8 + tc;
                uint32_t a0 = zsW[(m0 + gr) * ZS_W + kwb];
                uint32_t a1 = zsW[(m0 + gr + 8) * ZS_W + kwb];
                uint32_t a2 = zsW[(m0 + gr) * ZS_W + kwb + 4];
                uint32_t a3 = zsW[(m0 + gr + 8) * ZS_W + kwb + 4];
                #pragma unroll
                for (int nb = 0; nb < 6; nb++) {
                    int c = nb * 8 + gr;
                    uint32_t b0 = w2W[c * W2T_W + kwb];
                    uint32_t b1f = w2W[c * W2T_W + kwb + 4];
                    mma16816(acc[nb][0], acc[nb][1], acc[nb][2], acc[nb][3],
                             a0, a1, a2, a3, b0, b1f);
                }
            }

            int nodeA = node0 + m0 + gr;
            int nodeB = nodeA + 8;
            #pragma unroll
            for (int nb = 0; nb < 6; nb++) {
                int c = nb * 8 + 2 * tc;
                if (c < N_CLS) {
                    float bc = b2s[c];
                    if (nodeA < N_NODES) out[(size_t)nodeA * N_CLS + c] = acc[nb][0] + bc;
                    if (nodeB < N_NODES) out[(size_t)nodeB * N_CLS + c] = acc[nb][2] + bc;
                }
                if (c + 1 < N_CLS) {
                    float bc = b2s[c + 1];
                    if (nodeA < N_NODES) out[(size_t)nodeA * N_CLS + c + 1] = acc[nb][1] + bc;
                    if (nodeB < N_NODES) out[(size_t)nodeB * N_CLS + c + 1] = acc[nb][3] + bc;
                }
            }
        }
        __syncthreads();   // protect hs before next tile's staging
    }
}

// ---------------- launch ----------------
extern "C" void kernel_launch(void* const* d_in, const int* in_sizes, int n_in,
                              void* d_out, int out_size) {
    const float* x   = (const float*)d_in[0];
    const int*   src = (const int*)d_in[1];
    const int*   dst = (const int*)d_in[2];
    const float* W1  = (const float*)d_in[3];
    const float* b1  = (const float*)d_in[4];
    const float* W2  = (const float*)d_in[5];
    const float* b2  = (const float*)d_in[6];
    float* out = (float*)d_out;

    cudaFuncSetAttribute(mlp_mma_kernel, cudaFuncAttributeMaxDynamicSharedMemorySize,
                         MLP_SMEM_BYTES);

    float* p0 = nullptr;
    float* p1 = nullptr;
    cudaGetSymbolAddress((void**)&p0, g_buf0);
    cudaGetSymbolAddress((void**)&p1, g_buf1);

    int nb_edges = (N_EDGES + 255) / 256;
    int nb_prop = (N_NODES * 32 + 255) / 256;   // one warp per node

    count_kernel<<<nb_edges, 256>>>(dst);                 // launch 0
    scan_kernel<<<1, SCAN_T>>>();                         // launch 1 (scan+norm)
    fill_kernel<<<nb_edges, 256>>>(src, dst);             // launch 2 (+zero cnt)

    // t = 0 fused with init: writes g_buf1                // launch 3 (profiled)
    prop_first_kernel<<<nb_prop, 256>>>((const float4*)x, (float4*)p1);

    for (int t = 1; t < K_STEPS; t++) {
        const float* gin = (t & 1) ? p1 : p0;
        float* gout      = (t & 1) ? p0 : p1;
        prop_kernel<<<nb_prop, 256>>>((const float4*)gin, (float4*)gout,
                                      (const float4*)x, (t == K_STEPS - 1) ? 1 : 0);
    }
    // t=9 (odd) wrote p0 -> h lives in g_buf0 (fp32)
    mlp_mma_kernel<<<148, MLP_THREADS, MLP_SMEM_BYTES>>>(p0, W1, b1, W2, b2, out);
}

// round 10
// speedup vs baseline: 1.2800x; 1.0336x over previous
#include <cuda_runtime.h>
#include <cuda_bf16.h>
#include <cuda_fp16.h>
#include <math.h>
#include <stdint.h>

#define N_NODES 100000
#define N_EDGES 800000
#define D_DATA  100
#define H_DIM   256
#define N_CLS   47
#define K_STEPS 10
#define D_VEC   25          // D_DATA / 4 float4s per row

// ---------------- static device scratch ----------------
__device__ float g_buf0[(size_t)N_NODES * D_DATA];   // 40 MB
__device__ float g_buf1[(size_t)N_NODES * D_DATA];   // 40 MB
__device__ int   d_cnt[N_NODES];
__device__ int   d_ptr[N_NODES + 1];
__device__ int   d_cursor[N_NODES];
__device__ float d_norm[N_NODES];
__device__ float d_n2[N_NODES];
__device__ int   d_csr[N_EDGES];

// ---------------- CSR build ----------------
// d_cnt is zero at entry of every call (zero-init at load; fill_kernel re-zeros).
__global__ void count_kernel(const int* __restrict__ dst) {
    int e = blockIdx.x * blockDim.x + threadIdx.x;
    if (e < N_EDGES) atomicAdd(&d_cnt[dst[e]], 1);
}

#define SCAN_T 1024
#define SCAN_CH 98
__global__ void scan_kernel() {
    __shared__ int part[SCAN_T];
    int t = threadIdx.x;
    int beg = t * SCAN_CH;
    int end = beg + SCAN_CH; if (end > N_NODES) end = N_NODES;
    if (beg > N_NODES) beg = N_NODES;
    int s = 0;
    for (int i = beg; i < end; i++) s += d_cnt[i];
    part[t] = s;
    __syncthreads();
    for (int off = 1; off < SCAN_T; off <<= 1) {
        int v = (t >= off) ? part[t - off] : 0;
        __syncthreads();
        part[t] += v;
        __syncthreads();
    }
    int run = part[t] - s;
    for (int i = beg; i < end; i++) {
        d_ptr[i] = run;
        d_cursor[i] = run;
        int c = d_cnt[i];
        run += c;
        float nm = rsqrtf(fmaxf((float)c, 1.0f));
        d_norm[i] = nm;
        d_n2[i] = nm * nm;
    }
    if (t == SCAN_T - 1) d_ptr[N_NODES] = part[SCAN_T - 1];
}

__global__ void fill_kernel(const int* __restrict__ src, const int* __restrict__ dst) {
    int e = blockIdx.x * blockDim.x + threadIdx.x;
    if (e < N_EDGES) {
        int d = dst[e];
        int p = atomicAdd(&d_cursor[d], 1);
        d_csr[p] = src[e];
    }
    if (e < N_NODES) d_cnt[e] = 0;
}

// ---------------- propagation (64-thread blocks: straggler fix) ----------
__global__ void prop_first_kernel(const float4* __restrict__ x,
                                  float4* __restrict__ gout) {
    int warp = (blockIdx.x * blockDim.x + threadIdx.x) >> 5;
    int lane = threadIdx.x & 31;
    if (warp >= N_NODES) return;
    int beg = d_ptr[warp];
    int end = d_ptr[warp + 1];

    float a0 = 0.f, a1 = 0.f, a2 = 0.f, a3 = 0.f;
    bool act = lane < D_VEC;

    for (int base = beg; base < end; base += 32) {
        int n = end - base; if (n > 32) n = 32;
        int idx = (lane < n) ? d_csr[base + lane] : 0;
        #pragma unroll 4
        for (int e = 0; e < n; e++) {
            int s = __shfl_sync(0xffffffffu, idx, e);
            float ns = __ldg(&d_norm[s]);
            if (act) {
                float4 v = x[s * D_VEC + lane];
                a0 += ns * v.x; a1 += ns * v.y; a2 += ns * v.z; a3 += ns * v.w;
            }
        }
    }

    float s1 = 0.9f * d_n2[warp];
    float s2 = 0.1f * d_norm[warp];
    if (act) {
        float4 xv = x[warp * D_VEC + lane];
        float4 o;
        o.x = s1 * a0 + s2 * xv.x;
        o.y = s1 * a1 + s2 * xv.y;
        o.z = s1 * a2 + s2 * xv.z;
        o.w = s1 * a3 + s2 * xv.w;
        gout[warp * D_VEC + lane] = o;
    }
}

__global__ void prop_kernel(const float4* __restrict__ gin,
                            float4* __restrict__ gout,
                            const float4* __restrict__ x,
                            int last) {
    int warp = (blockIdx.x * blockDim.x + threadIdx.x) >> 5;
    int lane = threadIdx.x & 31;
    if (warp >= N_NODES) return;
    int beg = d_ptr[warp];
    int end = d_ptr[warp + 1];

    float a0 = 0.f, a1 = 0.f, a2 = 0.f, a3 = 0.f;
    bool act = lane < D_VEC;

    for (int base = beg; base < end; base += 32) {
        int n = end - base; if (n > 32) n = 32;
        int idx = (lane < n) ? d_csr[base + lane] : 0;
        #pragma unroll 4
        for (int e = 0; e < n; e++) {
            int s = __shfl_sync(0xffffffffu, idx, e);
            if (act) {
                float4 v = gin[s * D_VEC + lane];
                a0 += v.x; a1 += v.y; a2 += v.z; a3 += v.w;
            }
        }
    }

    float ni = d_norm[warp];
    float s1, s2;
    if (last) { s1 = 0.9f * ni;         s2 = 0.1f; }
    else      { s1 = 0.9f * d_n2[warp]; s2 = 0.1f * ni; }

    if (act) {
        float4 xv = __ldcs(&x[warp * D_VEC + lane]);
        float4 o;
        o.x = s1 * a0 + s2 * xv.x;
        o.y = s1 * a1 + s2 * xv.y;
        o.z = s1 * a2 + s2 * xv.z;
        o.w = s1 * a3 + s2 * xv.w;
        if (last) __stcs(&gout[warp * D_VEC + lane], o);
        else      gout[warp * D_VEC + lane] = o;
    }
}

// ---------------- MLP via warp-level mma.sync (fp16 in, fp32 accum) ----------
// 512 threads / 16 warps. Warp pair (2wp, 2wp+1) owns rows [wp*16, wp*16+16):
//   phase 1: warp half=0 does n-chunks {0,1}, half=1 does {2,3}
//   phase 2: half=0 does c-blocks {0,1,2}, half=1 does {3,4,5}
// Same total instructions as R9, 2x warps/SMSP for latency cover.
#define TILE_M 128
#define MLP_THREADS 512
#define HS_W   60            // words per hs row
#define W1T_W  60
#define ZS_W   132
#define W2T_W  132

#define OFF_HS   0
#define OFF_W1T  30720
#define OFF_ZS   92160
#define OFF_W2T  159744
#define OFF_B1   185088
#define OFF_B2   186112
#define MLP_SMEM_BYTES 186304

__device__ __forceinline__ void mma16816(float& c0, float& c1, float& c2, float& c3,
                                         uint32_t a0, uint32_t a1, uint32_t a2, uint32_t a3,
                                         uint32_t b0, uint32_t b1) {
    asm volatile(
        "mma.sync.aligned.m16n8k16.row.col.f32.f16.f16.f32 "
        "{%0,%1,%2,%3}, {%4,%5,%6,%7}, {%8,%9}, {%0,%1,%2,%3};"
        : "+f"(c0), "+f"(c1), "+f"(c2), "+f"(c3)
        : "r"(a0), "r"(a1), "r"(a2), "r"(a3), "r"(b0), "r"(b1));
}

__device__ __forceinline__ uint32_t pack_h2(float lo, float hi) {
    __half2 h = __floats2half2_rn(lo, hi);
    return *(uint32_t*)&h;
}

__global__ void __launch_bounds__(MLP_THREADS, 1)
mlp_mma_kernel(const float* __restrict__ h,
               const float* __restrict__ W1, const float* __restrict__ b1,
               const float* __restrict__ W2, const float* __restrict__ b2,
               float* __restrict__ out) {
    extern __shared__ char smc[];
    uint32_t* hsW  = (uint32_t*)(smc + OFF_HS);
    uint32_t* w1W  = (uint32_t*)(smc + OFF_W1T);
    uint32_t* zsW  = (uint32_t*)(smc + OFF_ZS);
    uint32_t* w2W  = (uint32_t*)(smc + OFF_W2T);
    float*    b1s  = (float*)(smc + OFF_B1);
    float*    b2s  = (float*)(smc + OFF_B2);

    int tid = threadIdx.x;
    int wid = tid >> 5, lane = tid & 31;
    int gr = lane >> 2, tc = lane & 3;     // fragment row-group / thread-in-group
    int wp = wid >> 1, half = wid & 1;     // row-group pair / work split
    int m0 = wp * 16;

    // ---- stage W1T [j][k], zero pad k >= 100 ----
    for (int i = tid; i < 256 * W1T_W; i += MLP_THREADS) {
        int j = i / W1T_W, kw = i % W1T_W;
        int k = kw * 2;
        float lo = (k     < D_DATA) ? W1[k * H_DIM + j]       : 0.f;
        float hi = (k + 1 < D_DATA) ? W1[(k + 1) * H_DIM + j] : 0.f;
        w1W[i] = pack_h2(lo, hi);
    }
    // ---- stage W2T [c][j], zero pad c >= 47, j >= 256 ----
    for (int i = tid; i < 48 * W2T_W; i += MLP_THREADS) {
        int c = i / W2T_W, jw = i % W2T_W;
        int j = jw * 2;
        float lo = (c < N_CLS && j     < H_DIM) ? W2[j * N_CLS + c]       : 0.f;
        float hi = (c < N_CLS && j + 1 < H_DIM) ? W2[(j + 1) * N_CLS + c] : 0.f;
        w2W[i] = pack_h2(lo, hi);
    }
    for (int i = tid; i < H_DIM; i += MLP_THREADS) b1s[i] = b1[i];
    if (tid < 48) b2s[tid] = (tid < N_CLS) ? b2[tid] : 0.f;
    __syncthreads();

    int n_tiles = (N_NODES + TILE_M - 1) / TILE_M;   // 782
    for (int tile = blockIdx.x; tile < n_tiles; tile += gridDim.x) {
        int node0 = tile * TILE_M;

        // ---- stage hs [m][k] fp16, zero pad ----
        for (int i = tid; i < TILE_M * HS_W; i += MLP_THREADS) {
            int m = i / HS_W, kw = i % HS_W;
            int k = kw * 2;
            int node = node0 + m;
            uint32_t v = 0;
            if (node < N_NODES && k < D_DATA) {
                float2 f = *(const float2*)(h + (size_t)node * D_DATA + k);
                v = pack_h2(f.x, f.y);
            }
            hsW[i] = v;
        }
        __syncthreads();

        // ---- phase 1: z = relu(h @ W1 + b1); 2 n-chunks of 64 per warp ----
        #pragma unroll 1
        for (int chh = 0; chh < 2; chh++) {
            int n0 = (half * 2 + chh) * 64;
            float acc[8][4];
            #pragma unroll
            for (int nb = 0; nb < 8; nb++)
                #pragma unroll
                for (int q = 0; q < 4; q++) acc[nb][q] = 0.f;

            #pragma unroll
            for (int kb = 0; kb < 7; kb++) {
                int kwb = kb * 8 + tc;
                uint32_t a0 = hsW[(m0 + gr) * HS_W + kwb];
                uint32_t a1 = hsW[(m0 + gr + 8) * HS_W + kwb];
                uint32_t a2 = hsW[(m0 + gr) * HS_W + kwb + 4];
                uint32_t a3 = hsW[(m0 + gr + 8) * HS_W + kwb + 4];
                #pragma unroll
                for (int nb = 0; nb < 8; nb++) {
                    int j = n0 + nb * 8 + gr;
                    uint32_t b0 = w1W[j * W1T_W + kwb];
                    uint32_t b1f = w1W[j * W1T_W + kwb + 4];
                    mma16816(acc[nb][0], acc[nb][1], acc[nb][2], acc[nb][3],
                             a0, a1, a2, a3, b0, b1f);
                }
            }
            // epilogue: bias + relu -> zs fp16
            #pragma unroll
            for (int nb = 0; nb < 8; nb++) {
                int j = n0 + nb * 8 + 2 * tc;
                float2 bb = *(const float2*)(b1s + j);
                float f0 = fmaxf(acc[nb][0] + bb.x, 0.f);
                float f1 = fmaxf(acc[nb][1] + bb.y, 0.f);
                float f2 = fmaxf(acc[nb][2] + bb.x, 0.f);
                float f3 = fmaxf(acc[nb][3] + bb.y, 0.f);
                int jw = (n0 + nb * 8) / 2 + tc;
                zsW[(m0 + gr) * ZS_W + jw]     = pack_h2(f0, f1);
                zsW[(m0 + gr + 8) * ZS_W + jw] = pack_h2(f2, f3);
            }
        }
        __syncthreads();   // both warps of a pair must finish zs rows

        // ---- phase 2: logits = z @ W2 + b2; 3 c-blocks per warp ----
        {
            float acc[3][4];
            #pragma unroll
            for (int nb = 0; nb < 3; nb++)
                #pragma unroll
                for (int q = 0; q < 4; q++) acc[nb][q] = 0.f;

            #pragma unroll 4
            for (int kb = 0; kb < 16; kb++) {
                int kwb = kb * 8 + tc;
                uint32_t a0 = zsW[(m0 + gr) * ZS_W + kwb];
                uint32_t a1 = zsW[(m0 + gr + 8) * ZS_W + kwb];
                uint32_t a2 = zsW[(m0 + gr) * ZS_W + kwb + 4];
                uint32_t a3 = zsW[(m0 + gr + 8) * ZS_W + kwb + 4];
                #pragma unroll
                for (int nb = 0; nb < 3; nb++) {
                    int c = (half * 3 + nb) * 8 + gr;
                    uint32_t b0 = w2W[c * W2T_W + kwb];
                    uint32_t b1f = w2W[c * W2T_W + kwb + 4];
                    mma16816(acc[nb][0], acc[nb][1], acc[nb][2], acc[nb][3],
                             a0, a1, a2, a3, b0, b1f);
                }
            }

            int nodeA = node0 + m0 + gr;
            int nodeB = nodeA + 8;
            #pragma unroll
            for (int nb = 0; nb < 3; nb++) {
                int c = (half * 3 + nb) * 8 + 2 * tc;
                if (c < N_CLS) {
                    float bc = b2s[c];
                    if (nodeA < N_NODES) out[(size_t)nodeA * N_CLS + c] = acc[nb][0] + bc;
                    if (nodeB < N_NODES) out[(size_t)nodeB * N_CLS + c] = acc[nb][2] + bc;
                }
                if (c + 1 < N_CLS) {
                    float bc = b2s[c + 1];
                    if (nodeA < N_NODES) out[(size_t)nodeA * N_CLS + c + 1] = acc[nb][1] + bc;
                    if (nodeB < N_NODES) out[(size_t)nodeB * N_CLS + c + 1] = acc[nb][3] + bc;
                }
            }
        }
        __syncthreads();   // protect hs/zs before next tile's staging
    }
}

// ---------------- launch ----------------
extern "C" void kernel_launch(void* const* d_in, const int* in_sizes, int n_in,
                              void* d_out, int out_size) {
    const float* x   = (const float*)d_in[0];
    const int*   src = (const int*)d_in[1];
    const int*   dst = (const int*)d_in[2];
    const float* W1  = (const float*)d_in[3];
    const float* b1  = (const float*)d_in[4];
    const float* W2  = (const float*)d_in[5];
    const float* b2  = (const float*)d_in[6];
    float* out = (float*)d_out;

    cudaFuncSetAttribute(mlp_mma_kernel, cudaFuncAttributeMaxDynamicSharedMemorySize,
                         MLP_SMEM_BYTES);

    float* p0 = nullptr;
    float* p1 = nullptr;
    cudaGetSymbolAddress((void**)&p0, g_buf0);
    cudaGetSymbolAddress((void**)&p1, g_buf1);

    int nb_edges = (N_EDGES + 255) / 256;
    int nb_prop = (N_NODES * 32 + 63) / 64;     // 64-thread blocks, warp per node

    count_kernel<<<nb_edges, 256>>>(dst);                 // launch 0
    scan_kernel<<<1, SCAN_T>>>();                         // launch 1 (scan+norm)
    fill_kernel<<<nb_edges, 256>>>(src, dst);             // launch 2 (+zero cnt)

    // t = 0 fused with init: writes g_buf1                // launch 3 (profiled)
    prop_first_kernel<<<nb_prop, 64>>>((const float4*)x, (float4*)p1);

    for (int t = 1; t < K_STEPS; t++) {
        const float* gin = (t & 1) ? p1 : p0;
        float* gout      = (t & 1) ? p0 : p1;
        prop_kernel<<<nb_prop, 64>>>((const float4*)gin, (float4*)gout,
                                     (const float4*)x, (t == K_STEPS - 1) ? 1 : 0);
    }
    // t=9 (odd) wrote p0 -> h lives in g_buf0 (fp32)
    mlp_mma_kernel<<<148, MLP_THREADS, MLP_SMEM_BYTES>>>(p0, W1, b1, W2, b2, out);
}